// round 1
// baseline (speedup 1.0000x reference)
#include <cuda_runtime.h>
#include <cuda_bf16.h>
#include <cstdint>
#include <cstdio>

// ---------------------------------------------------------------------------
// DrugEncoder: only graph_repr is returned by the reference, so the whole
// bond-angle branch (angle_hidden, ba_src/ba_dst, emlp_*, e_ln_*) is dead code.
// Live pipeline:
//   node_h = node_hidden @ W + b          [NA,128]
//   edge_h = edge_hidden @ W + b          [NB,128]
//   agg_n[d] += node_h[ab_src] + edge_h   (scatter-sum over bonds)
//   h1 = relu(agg_n @ W1 + b1)            [NA,256]
//   h  = h1 @ W2 + b2 ; h = relu(LN(h)) ; node_out = node_h + h
//   out[g] = mean over atoms of node_out  (node_graph_id)
// node_out is never materialized: LN+relu+residual+pool fused into GEMM3 epilogue.
// ---------------------------------------------------------------------------

#define NA 500000
#define NB 1000000
#define NG 16384
#define HD 128

// scratch (device globals: no allocations allowed)
__device__ float g_proj[(size_t)(NA + NB) * HD];  // node_h rows [0,NA), edge_h rows [NA,NA+NB)
__device__ float g_agg[(size_t)NA * HD];
__device__ float g_h1[(size_t)NA * 256];
__device__ float g_cnt[NG];

// ---------------------------------------------------------------------------
// zero scratch + output
// ---------------------------------------------------------------------------
__global__ void zero_kernel(float4* __restrict__ out4) {
    size_t i = (size_t)blockIdx.x * blockDim.x + threadIdx.x;
    size_t stride = (size_t)gridDim.x * blockDim.x;
    float4 z = make_float4(0.f, 0.f, 0.f, 0.f);
    float4* agg4 = (float4*)g_agg;
    const size_t nagg4 = (size_t)NA * HD / 4;
    for (size_t j = i; j < nagg4; j += stride) agg4[j] = z;
    const size_t nout4 = (size_t)NG * HD / 4;
    for (size_t j = i; j < nout4; j += stride) out4[j] = z;
    float4* cnt4 = (float4*)g_cnt;
    for (size_t j = i; j < NG / 4; j += stride) cnt4[j] = z;
}

// ---------------------------------------------------------------------------
// Tiled SGEMM: Y[nrows,N] = act(X[nrows,K] @ W[K,N] + bias)
// Block: 64 rows x 128 cols, 256 threads, KT=32 k-tiles.
// Thread (tx,ty): tx in [0,32) -> 4 cols (float4), ty in [0,8) -> 8 rows.
// ---------------------------------------------------------------------------
#define KT 32

template <bool RELU>
__global__ __launch_bounds__(256) void gemm_bias_kernel(
    const float* __restrict__ X, const float* __restrict__ W,
    const float* __restrict__ bias, float* __restrict__ Y,
    int nrows, int K, int N)
{
    __shared__ float Ws[KT][128];
    __shared__ float Xs[64][KT];

    const int t = threadIdx.x;
    const int tx = t & 31;
    const int ty = t >> 5;
    const int rowbase = blockIdx.x * 64;
    const int colbase = blockIdx.y * 128;

    float acc[8][4];
#pragma unroll
    for (int r = 0; r < 8; r++)
#pragma unroll
        for (int c = 0; c < 4; c++) acc[r][c] = 0.f;

    for (int kt = 0; kt < K; kt += KT) {
        // load W tile: KT x 128 = 1024 float4
#pragma unroll
        for (int p = 0; p < 4; p++) {
            int idx4 = t + p * 256;
            int r = idx4 >> 5, c4 = idx4 & 31;
            *(float4*)&Ws[r][c4 * 4] =
                *(const float4*)&W[(size_t)(kt + r) * N + colbase + c4 * 4];
        }
        // load X tile: 64 x KT = 512 float4
#pragma unroll
        for (int p = 0; p < 2; p++) {
            int idx4 = t + p * 256;
            int r = idx4 >> 3, c4 = idx4 & 7;
            int gr = rowbase + r;
            float4 v = make_float4(0.f, 0.f, 0.f, 0.f);
            if (gr < nrows) v = *(const float4*)&X[(size_t)gr * K + kt + c4 * 4];
            *(float4*)&Xs[r][c4 * 4] = v;
        }
        __syncthreads();
#pragma unroll
        for (int k = 0; k < KT; k++) {
            float4 w = *(float4*)&Ws[k][tx * 4];
#pragma unroll
            for (int r = 0; r < 8; r++) {
                float x = Xs[ty * 8 + r][k];
                acc[r][0] += x * w.x;
                acc[r][1] += x * w.y;
                acc[r][2] += x * w.z;
                acc[r][3] += x * w.w;
            }
        }
        __syncthreads();
    }

    float4 b4 = *(const float4*)&bias[colbase + tx * 4];
#pragma unroll
    for (int r = 0; r < 8; r++) {
        int gr = rowbase + ty * 8 + r;
        if (gr >= nrows) break;
        float4 o;
        o.x = acc[r][0] + b4.x;
        o.y = acc[r][1] + b4.y;
        o.z = acc[r][2] + b4.z;
        o.w = acc[r][3] + b4.w;
        if (RELU) {
            o.x = fmaxf(o.x, 0.f); o.y = fmaxf(o.y, 0.f);
            o.z = fmaxf(o.z, 0.f); o.w = fmaxf(o.w, 0.f);
        }
        *(float4*)&Y[(size_t)gr * N + colbase + tx * 4] = o;
    }
}

// ---------------------------------------------------------------------------
// Scatter: agg[ab_dst[e]] += node_h[ab_src[e]] + edge_h[e]
// One warp per bond; each lane owns one float4 (4 of 128 cols).
// Vector reduction: red.global.add.v4.f32 (sm_90+).
// ---------------------------------------------------------------------------
__global__ __launch_bounds__(256) void scatter_kernel(
    const int* __restrict__ ab_src, const int* __restrict__ ab_dst)
{
    int b = blockIdx.x * 8 + (threadIdx.x >> 5);
    if (b >= NB) return;
    int lane = threadIdx.x & 31;
    int s = ab_src[b];
    int d = ab_dst[b];
    float4 a = *(const float4*)&g_proj[(size_t)s * HD + lane * 4];
    float4 e = *(const float4*)&g_proj[((size_t)NA + b) * HD + lane * 4];
    float4 v;
    v.x = a.x + e.x; v.y = a.y + e.y; v.z = a.z + e.z; v.w = a.w + e.w;
    float* dst = &g_agg[(size_t)d * HD + lane * 4];
    asm volatile("red.global.add.v4.f32 [%0], {%1,%2,%3,%4};"
                 :: "l"(dst), "f"(v.x), "f"(v.y), "f"(v.z), "f"(v.w)
                 : "memory");
}

// ---------------------------------------------------------------------------
// GEMM3 fused: h = h1 @ W2 + b2 ; h = relu(LN(h)) ; node_out = node_h + h ;
// out[gid] += node_out ; cnt[gid] += 1.  (K=256, N=128, one col-block)
// Each warp owns 8 complete rows -> LN stats via warp shuffle reduce.
// ---------------------------------------------------------------------------
__global__ __launch_bounds__(256) void gemm_ln_pool_kernel(
    const float* __restrict__ X,      // g_h1 [NA,256]
    const float* __restrict__ W,      // nmlp_w2 [256,128]
    const float* __restrict__ bias,   // nmlp_b2 [128]
    const float* __restrict__ ln_g, const float* __restrict__ ln_b,
    const int* __restrict__ gid,
    float* __restrict__ out)          // [NG,128] (accumulated)
{
    __shared__ float Ws[KT][128];
    __shared__ float Xs[64][KT];

    const int K = 256, N = 128;
    const int t = threadIdx.x;
    const int tx = t & 31;
    const int ty = t >> 5;
    const int rowbase = blockIdx.x * 64;

    float acc[8][4];
#pragma unroll
    for (int r = 0; r < 8; r++)
#pragma unroll
        for (int c = 0; c < 4; c++) acc[r][c] = 0.f;

    for (int kt = 0; kt < K; kt += KT) {
#pragma unroll
        for (int p = 0; p < 4; p++) {
            int idx4 = t + p * 256;
            int r = idx4 >> 5, c4 = idx4 & 31;
            *(float4*)&Ws[r][c4 * 4] =
                *(const float4*)&W[(size_t)(kt + r) * N + c4 * 4];
        }
#pragma unroll
        for (int p = 0; p < 2; p++) {
            int idx4 = t + p * 256;
            int r = idx4 >> 3, c4 = idx4 & 7;
            int gr = rowbase + r;
            float4 v = make_float4(0.f, 0.f, 0.f, 0.f);
            if (gr < NA) v = *(const float4*)&X[(size_t)gr * K + kt + c4 * 4];
            *(float4*)&Xs[r][c4 * 4] = v;
        }
        __syncthreads();
#pragma unroll
        for (int k = 0; k < KT; k++) {
            float4 w = *(float4*)&Ws[k][tx * 4];
#pragma unroll
            for (int r = 0; r < 8; r++) {
                float x = Xs[ty * 8 + r][k];
                acc[r][0] += x * w.x;
                acc[r][1] += x * w.y;
                acc[r][2] += x * w.z;
                acc[r][3] += x * w.w;
            }
        }
        __syncthreads();
    }

    float4 b4 = *(const float4*)&bias[tx * 4];
    float4 g4 = *(const float4*)&ln_g[tx * 4];
    float4 e4 = *(const float4*)&ln_b[tx * 4];

#pragma unroll
    for (int r = 0; r < 8; r++) {
        int gr = rowbase + ty * 8 + r;
        if (gr >= NA) break;
        float4 h;
        h.x = acc[r][0] + b4.x;
        h.y = acc[r][1] + b4.y;
        h.z = acc[r][2] + b4.z;
        h.w = acc[r][3] + b4.w;
        // LayerNorm stats across the 128-wide row (held by this warp)
        float s = h.x + h.y + h.z + h.w;
        float s2 = h.x * h.x + h.y * h.y + h.z * h.z + h.w * h.w;
#pragma unroll
        for (int off = 16; off > 0; off >>= 1) {
            s  += __shfl_xor_sync(0xffffffffu, s, off);
            s2 += __shfl_xor_sync(0xffffffffu, s2, off);
        }
        float mu = s * (1.f / 128.f);
        float var = s2 * (1.f / 128.f) - mu * mu;
        float rstd = rsqrtf(var + 1e-5f);
        float4 nh = *(const float4*)&g_proj[(size_t)gr * HD + tx * 4];
        float4 o;
        o.x = fmaxf((h.x - mu) * rstd * g4.x + e4.x, 0.f) + nh.x;
        o.y = fmaxf((h.y - mu) * rstd * g4.y + e4.y, 0.f) + nh.y;
        o.z = fmaxf((h.z - mu) * rstd * g4.z + e4.z, 0.f) + nh.z;
        o.w = fmaxf((h.w - mu) * rstd * g4.w + e4.w, 0.f) + nh.w;
        int g = gid[gr];
        float* dst = &out[(size_t)g * HD + tx * 4];
        asm volatile("red.global.add.v4.f32 [%0], {%1,%2,%3,%4};"
                     :: "l"(dst), "f"(o.x), "f"(o.y), "f"(o.z), "f"(o.w)
                     : "memory");
        if (tx == 0) atomicAdd(&g_cnt[g], 1.0f);
    }
}

// ---------------------------------------------------------------------------
// finalize: out[g,:] /= max(cnt[g], 1)
// ---------------------------------------------------------------------------
__global__ void finalize_kernel(float4* __restrict__ out4) {
    int i = blockIdx.x * blockDim.x + threadIdx.x;  // over NG*32 float4s
    if (i >= NG * (HD / 4)) return;
    int g = i >> 5;
    float c = fmaxf(g_cnt[g], 1.0f);
    float inv = 1.0f / c;
    float4 v = out4[i];
    v.x *= inv; v.y *= inv; v.z *= inv; v.w *= inv;
    out4[i] = v;
}

// ---------------------------------------------------------------------------
extern "C" void kernel_launch(void* const* d_in, const int* in_sizes, int n_in,
                              void* d_out, int out_size)
{
    const float* node_hidden = (const float*)d_in[0];
    const float* edge_hidden = (const float*)d_in[1];
    // d_in[2] angle_hidden : dead code
    const float* atom_w = (const float*)d_in[3];
    const float* atom_b = (const float*)d_in[4];
    const float* nmlp_w1 = (const float*)d_in[5];
    const float* nmlp_b1 = (const float*)d_in[6];
    const float* nmlp_w2 = (const float*)d_in[7];
    const float* nmlp_b2 = (const float*)d_in[8];
    const float* n_ln_g = (const float*)d_in[9];
    const float* n_ln_b = (const float*)d_in[10];
    // d_in[11..16] emlp_* / e_ln_* : dead code
    const int* ab_src = (const int*)d_in[17];
    const int* ab_dst = (const int*)d_in[18];
    // d_in[19..20] ba_src/ba_dst : dead code
    const int* node_graph_id = (const int*)d_in[21];
    float* out = (float*)d_out;

    float *p_proj, *p_agg, *p_h1;
    cudaGetSymbolAddress((void**)&p_proj, g_proj);
    cudaGetSymbolAddress((void**)&p_agg, g_agg);
    cudaGetSymbolAddress((void**)&p_h1, g_h1);

    // 1. zero scratch accumulators + output
    zero_kernel<<<2368, 256>>>((float4*)out);

    // 2. projections (shared weight) -> g_proj
    gemm_bias_kernel<false><<<dim3((NA + 63) / 64, 1), 256>>>(
        node_hidden, atom_w, atom_b, p_proj, NA, 128, 128);
    gemm_bias_kernel<false><<<dim3((NB + 63) / 64, 1), 256>>>(
        edge_hidden, atom_w, atom_b, p_proj + (size_t)NA * HD, NB, 128, 128);

    // 3. bond scatter-sum -> g_agg
    scatter_kernel<<<(NB + 7) / 8, 256>>>(ab_src, ab_dst);

    // 4. MLP layer 1 (relu) -> g_h1
    gemm_bias_kernel<true><<<dim3((NA + 63) / 64, 2), 256>>>(
        p_agg, nmlp_w1, nmlp_b1, p_h1, NA, 128, 256);

    // 5. MLP layer 2 + LN + relu + residual + mean-pool accumulate -> out
    gemm_ln_pool_kernel<<<(NA + 63) / 64, 256>>>(
        p_h1, nmlp_w2, nmlp_b2, n_ln_g, n_ln_b, node_graph_id, out);

    // 6. divide by per-graph atom counts
    finalize_kernel<<<(NG * (HD / 4) + 255) / 256, 256>>>((float4*)out);
}

// round 2
// speedup vs baseline: 2.8860x; 2.8860x over previous
#include <cuda_runtime.h>
#include <cuda_bf16.h>
#include <cstdint>

// ---------------------------------------------------------------------------
// DrugEncoder: bond-angle branch is dead code (reference deletes edge_out).
// Live pipeline:
//   node_h = node_hidden @ W + b ; edge_h = edge_hidden @ W + b
//   agg[d] += node_h[ab_src] + edge_h           (bond scatter-sum)
//   h1 = relu(agg @ W1 + b1)
//   h  = h1 @ W2 + b2 ; h = relu(LN(h)) ; node_out = node_h + h
//   out[g] = mean over atoms of node_out
// GEMMs run on tensor cores (TF32 mma.sync, RN-converted inputs, fp32 accum).
// mlp2 GEMM fuses bias+LN+relu+residual+mean-pool in-register (no C smem).
// ---------------------------------------------------------------------------

#define NA 500000
#define NB 1000000
#define NG 16384
#define HD 128

__device__ float g_proj[(size_t)(NA + NB) * HD];  // node_h | edge_h
__device__ float g_agg[(size_t)NA * HD];
__device__ float g_h1[(size_t)NA * 256];
__device__ float g_cnt[NG];

// ---------------------------------------------------------------------------
__device__ __forceinline__ uint32_t f2tf(float x) {
    uint32_t r;
    asm("cvt.rna.tf32.f32 %0, %1;" : "=r"(r) : "f"(x));
    return r;
}

__device__ __forceinline__ void mma_tf32(float* c, const uint32_t* a, const uint32_t* b) {
    asm volatile(
        "mma.sync.aligned.m16n8k8.row.col.f32.tf32.tf32.f32 "
        "{%0,%1,%2,%3}, {%4,%5,%6,%7}, {%8,%9}, {%0,%1,%2,%3};"
        : "+f"(c[0]), "+f"(c[1]), "+f"(c[2]), "+f"(c[3])
        : "r"(a[0]), "r"(a[1]), "r"(a[2]), "r"(a[3]), "r"(b[0]), "r"(b[1]));
}

// ---------------------------------------------------------------------------
__global__ void zero_kernel(float4* __restrict__ out4) {
    size_t i = (size_t)blockIdx.x * blockDim.x + threadIdx.x;
    size_t stride = (size_t)gridDim.x * blockDim.x;
    float4 z = make_float4(0.f, 0.f, 0.f, 0.f);
    float4* agg4 = (float4*)g_agg;
    const size_t nagg4 = (size_t)NA * HD / 4;
    for (size_t j = i; j < nagg4; j += stride) agg4[j] = z;
    const size_t nout4 = (size_t)NG * HD / 4;
    for (size_t j = i; j < nout4; j += stride) out4[j] = z;
    float4* cnt4 = (float4*)g_cnt;
    for (size_t j = i; j < NG / 4; j += stride) cnt4[j] = z;
}

// ---------------------------------------------------------------------------
// TF32 tensor-core GEMM: Y[nrows,N] = act(X[nrows,K] @ W[K,N] + bias)
// Block tile 128x128, 8 warps as 4(m) x 2(n), warp tile 32x64, KT=32.
// ---------------------------------------------------------------------------
template <bool RELU>
__global__ __launch_bounds__(256) void gemm_tf32_kernel(
    const float* __restrict__ X, const float* __restrict__ W,
    const float* __restrict__ bias, float* __restrict__ Y,
    int nrows, int K, int N)
{
    __shared__ uint32_t As[128][36];   // pad 4 -> conflict-free frag reads
    __shared__ uint32_t Ws[32][132];

    const int t = threadIdx.x;
    const int lane = t & 31;
    const int wid = t >> 5;
    const int wm = wid & 3;
    const int wn = wid >> 2;
    const int rowbase = blockIdx.x * 128;
    const int colbase = blockIdx.y * 128;

    float c[2][8][4];
#pragma unroll
    for (int i = 0; i < 2; i++)
#pragma unroll
        for (int j = 0; j < 8; j++)
#pragma unroll
            for (int k = 0; k < 4; k++) c[i][j][k] = 0.f;

    for (int kt = 0; kt < K; kt += 32) {
        // W tile: 32 x 128
#pragma unroll
        for (int p = 0; p < 4; p++) {
            int idx4 = t + p * 256;
            int r = idx4 >> 5, c4 = idx4 & 31;
            float4 w = *(const float4*)&W[(size_t)(kt + r) * N + colbase + c4 * 4];
            *(uint4*)&Ws[r][c4 * 4] =
                make_uint4(f2tf(w.x), f2tf(w.y), f2tf(w.z), f2tf(w.w));
        }
        // A tile: 128 x 32
#pragma unroll
        for (int p = 0; p < 4; p++) {
            int idx4 = t + p * 256;
            int r = idx4 >> 3, c4 = idx4 & 7;
            int gr = rowbase + r;
            float4 v = make_float4(0.f, 0.f, 0.f, 0.f);
            if (gr < nrows) v = *(const float4*)&X[(size_t)gr * K + kt + c4 * 4];
            *(uint4*)&As[r][c4 * 4] =
                make_uint4(f2tf(v.x), f2tf(v.y), f2tf(v.z), f2tf(v.w));
        }
        __syncthreads();

#pragma unroll
        for (int ks = 0; ks < 4; ks++) {
            const int k0 = ks * 8;
            uint32_t a[2][4], b[8][2];
#pragma unroll
            for (int fm = 0; fm < 2; fm++) {
                int ar = wm * 32 + fm * 16 + (lane >> 2);
                int ac = k0 + (lane & 3);
                a[fm][0] = As[ar][ac];
                a[fm][1] = As[ar + 8][ac];
                a[fm][2] = As[ar][ac + 4];
                a[fm][3] = As[ar + 8][ac + 4];
            }
#pragma unroll
            for (int fn = 0; fn < 8; fn++) {
                int bc = wn * 64 + fn * 8 + (lane >> 2);
                int br = k0 + (lane & 3);
                b[fn][0] = Ws[br][bc];
                b[fn][1] = Ws[br + 4][bc];
            }
#pragma unroll
            for (int fm = 0; fm < 2; fm++)
#pragma unroll
                for (int fn = 0; fn < 8; fn++) mma_tf32(c[fm][fn], a[fm], b[fn]);
        }
        __syncthreads();
    }

    // epilogue: bias (+relu), fragment-layout stores
#pragma unroll
    for (int fm = 0; fm < 2; fm++) {
        int r0 = rowbase + wm * 32 + fm * 16 + (lane >> 2);
#pragma unroll
        for (int fn = 0; fn < 8; fn++) {
            int col = colbase + wn * 64 + fn * 8 + 2 * (lane & 3);
            float bx = bias[col], by = bias[col + 1];
            float2 v0 = make_float2(c[fm][fn][0] + bx, c[fm][fn][1] + by);
            float2 v1 = make_float2(c[fm][fn][2] + bx, c[fm][fn][3] + by);
            if (RELU) {
                v0.x = fmaxf(v0.x, 0.f); v0.y = fmaxf(v0.y, 0.f);
                v1.x = fmaxf(v1.x, 0.f); v1.y = fmaxf(v1.y, 0.f);
            }
            if (r0 < nrows)     *(float2*)&Y[(size_t)r0 * N + col] = v0;
            if (r0 + 8 < nrows) *(float2*)&Y[(size_t)(r0 + 8) * N + col] = v1;
        }
    }
}

// ---------------------------------------------------------------------------
// Scatter: agg[ab_dst[e]] += node_h[ab_src[e]] + edge_h[e]  (one warp/bond)
// ---------------------------------------------------------------------------
__global__ __launch_bounds__(256) void scatter_kernel(
    const int* __restrict__ ab_src, const int* __restrict__ ab_dst)
{
    int b = blockIdx.x * 8 + (threadIdx.x >> 5);
    if (b >= NB) return;
    int lane = threadIdx.x & 31;
    int s = ab_src[b];
    int d = ab_dst[b];
    float4 a = *(const float4*)&g_proj[(size_t)s * HD + lane * 4];
    float4 e = *(const float4*)&g_proj[((size_t)NA + b) * HD + lane * 4];
    float4 v;
    v.x = a.x + e.x; v.y = a.y + e.y; v.z = a.z + e.z; v.w = a.w + e.w;
    float* dst = &g_agg[(size_t)d * HD + lane * 4];
    asm volatile("red.global.add.v4.f32 [%0], {%1,%2,%3,%4};"
                 :: "l"(dst), "f"(v.x), "f"(v.y), "f"(v.z), "f"(v.w)
                 : "memory");
}

// ---------------------------------------------------------------------------
// mlp2 fused (TF32 mma): h = h1 @ W2 + b2 ; relu(LN(h)) ; +node_h ; pool.
// K=256, N=128. LN row stats: quad shuffle + 4KB cross-warp smem reduce.
// ---------------------------------------------------------------------------
__global__ __launch_bounds__(256) void gemm_ln_pool_tf32_kernel(
    const float* __restrict__ X,      // g_h1 [NA,256]
    const float* __restrict__ W,      // [256,128]
    const float* __restrict__ bias,
    const float* __restrict__ ln_g, const float* __restrict__ ln_b,
    const int* __restrict__ gid,
    float* __restrict__ out)
{
    __shared__ uint32_t As[128][36];
    __shared__ uint32_t Ws[32][132];
    __shared__ float2 red[2][128];    // [warp_n][row_local] = (sum, sumsq)

    const int K = 256, N = 128;
    const int t = threadIdx.x;
    const int lane = t & 31;
    const int wid = t >> 5;
    const int wm = wid & 3;
    const int wn = wid >> 2;
    const int rowbase = blockIdx.x * 128;

    float c[2][8][4];
#pragma unroll
    for (int i = 0; i < 2; i++)
#pragma unroll
        for (int j = 0; j < 8; j++)
#pragma unroll
            for (int k = 0; k < 4; k++) c[i][j][k] = 0.f;

    for (int kt = 0; kt < K; kt += 32) {
#pragma unroll
        for (int p = 0; p < 4; p++) {
            int idx4 = t + p * 256;
            int r = idx4 >> 5, c4 = idx4 & 31;
            float4 w = *(const float4*)&W[(size_t)(kt + r) * N + c4 * 4];
            *(uint4*)&Ws[r][c4 * 4] =
                make_uint4(f2tf(w.x), f2tf(w.y), f2tf(w.z), f2tf(w.w));
        }
#pragma unroll
        for (int p = 0; p < 4; p++) {
            int idx4 = t + p * 256;
            int r = idx4 >> 3, c4 = idx4 & 7;
            int gr = rowbase + r;
            float4 v = make_float4(0.f, 0.f, 0.f, 0.f);
            if (gr < NA) v = *(const float4*)&X[(size_t)gr * K + kt + c4 * 4];
            *(uint4*)&As[r][c4 * 4] =
                make_uint4(f2tf(v.x), f2tf(v.y), f2tf(v.z), f2tf(v.w));
        }
        __syncthreads();

#pragma unroll
        for (int ks = 0; ks < 4; ks++) {
            const int k0 = ks * 8;
            uint32_t a[2][4], b[8][2];
#pragma unroll
            for (int fm = 0; fm < 2; fm++) {
                int ar = wm * 32 + fm * 16 + (lane >> 2);
                int ac = k0 + (lane & 3);
                a[fm][0] = As[ar][ac];
                a[fm][1] = As[ar + 8][ac];
                a[fm][2] = As[ar][ac + 4];
                a[fm][3] = As[ar + 8][ac + 4];
            }
#pragma unroll
            for (int fn = 0; fn < 8; fn++) {
                int bc = wn * 64 + fn * 8 + (lane >> 2);
                int br = k0 + (lane & 3);
                b[fn][0] = Ws[br][bc];
                b[fn][1] = Ws[br + 4][bc];
            }
#pragma unroll
            for (int fm = 0; fm < 2; fm++)
#pragma unroll
                for (int fn = 0; fn < 8; fn++) mma_tf32(c[fm][fn], a[fm], b[fn]);
        }
        __syncthreads();
    }

    // ---- epilogue: bias, LN stats, relu(LN)+residual, pool ----
    // add bias into fragments
#pragma unroll
    for (int fn = 0; fn < 8; fn++) {
        int col = wn * 64 + fn * 8 + 2 * (lane & 3);
        float bx = bias[col], by = bias[col + 1];
#pragma unroll
        for (int fm = 0; fm < 2; fm++) {
            c[fm][fn][0] += bx; c[fm][fn][1] += by;
            c[fm][fn][2] += bx; c[fm][fn][3] += by;
        }
    }
    // per-row partial (sum, sumsq): each thread's 16 values for each of 4 rows
#pragma unroll
    for (int fm = 0; fm < 2; fm++) {
#pragma unroll
        for (int h = 0; h < 2; h++) {
            int row_local = wm * 32 + fm * 16 + (lane >> 2) + h * 8;
            float s = 0.f, q = 0.f;
#pragma unroll
            for (int fn = 0; fn < 8; fn++) {
                float v0 = c[fm][fn][2 * h + 0];
                float v1 = c[fm][fn][2 * h + 1];
                s += v0 + v1;
                q += v0 * v0 + v1 * v1;
            }
            // reduce within quad (lanes sharing this row)
            s += __shfl_xor_sync(0xffffffffu, s, 1);
            q += __shfl_xor_sync(0xffffffffu, q, 1);
            s += __shfl_xor_sync(0xffffffffu, s, 2);
            q += __shfl_xor_sync(0xffffffffu, q, 2);
            if ((lane & 3) == 0) red[wn][row_local] = make_float2(s, q);
        }
    }
    __syncthreads();

#pragma unroll
    for (int fm = 0; fm < 2; fm++) {
#pragma unroll
        for (int h = 0; h < 2; h++) {
            int row_local = wm * 32 + fm * 16 + (lane >> 2) + h * 8;
            int gr = rowbase + row_local;
            if (gr >= NA) continue;
            float2 p0 = red[0][row_local];
            float2 p1 = red[1][row_local];
            float mu = (p0.x + p1.x) * (1.f / 128.f);
            float var = (p0.y + p1.y) * (1.f / 128.f) - mu * mu;
            float rstd = rsqrtf(var + 1e-5f);
            int g = gid[gr];
#pragma unroll
            for (int fn = 0; fn < 8; fn++) {
                int col = wn * 64 + fn * 8 + 2 * (lane & 3);
                float lg0 = ln_g[col], lg1 = ln_g[col + 1];
                float lb0 = ln_b[col], lb1 = ln_b[col + 1];
                float2 nh = *(const float2*)&g_proj[(size_t)gr * HD + col];
                float v0 = c[fm][fn][2 * h + 0];
                float v1 = c[fm][fn][2 * h + 1];
                float o0 = fmaxf((v0 - mu) * rstd * lg0 + lb0, 0.f) + nh.x;
                float o1 = fmaxf((v1 - mu) * rstd * lg1 + lb1, 0.f) + nh.y;
                float* dst = &out[(size_t)g * HD + col];
                asm volatile("red.global.add.v2.f32 [%0], {%1,%2};"
                             :: "l"(dst), "f"(o0), "f"(o1) : "memory");
            }
            if ((lane & 3) == 0 && wn == 0) atomicAdd(&g_cnt[g], 1.0f);
        }
    }
}

// ---------------------------------------------------------------------------
__global__ void finalize_kernel(float4* __restrict__ out4) {
    int i = blockIdx.x * blockDim.x + threadIdx.x;
    if (i >= NG * (HD / 4)) return;
    int g = i >> 5;
    float inv = 1.0f / fmaxf(g_cnt[g], 1.0f);
    float4 v = out4[i];
    v.x *= inv; v.y *= inv; v.z *= inv; v.w *= inv;
    out4[i] = v;
}

// ---------------------------------------------------------------------------
extern "C" void kernel_launch(void* const* d_in, const int* in_sizes, int n_in,
                              void* d_out, int out_size)
{
    const float* node_hidden = (const float*)d_in[0];
    const float* edge_hidden = (const float*)d_in[1];
    const float* atom_w = (const float*)d_in[3];
    const float* atom_b = (const float*)d_in[4];
    const float* nmlp_w1 = (const float*)d_in[5];
    const float* nmlp_b1 = (const float*)d_in[6];
    const float* nmlp_w2 = (const float*)d_in[7];
    const float* nmlp_b2 = (const float*)d_in[8];
    const float* n_ln_g = (const float*)d_in[9];
    const float* n_ln_b = (const float*)d_in[10];
    const int* ab_src = (const int*)d_in[17];
    const int* ab_dst = (const int*)d_in[18];
    const int* node_graph_id = (const int*)d_in[21];
    float* out = (float*)d_out;

    float *p_proj, *p_agg, *p_h1;
    cudaGetSymbolAddress((void**)&p_proj, g_proj);
    cudaGetSymbolAddress((void**)&p_agg, g_agg);
    cudaGetSymbolAddress((void**)&p_h1, g_h1);

    // 1. zero accumulators + output
    zero_kernel<<<2368, 256>>>((float4*)out);

    // 2. projections (shared weight)
    gemm_tf32_kernel<false><<<dim3((NA + 127) / 128, 1), 256>>>(
        node_hidden, atom_w, atom_b, p_proj, NA, 128, 128);
    gemm_tf32_kernel<false><<<dim3((NB + 127) / 128, 1), 256>>>(
        edge_hidden, atom_w, atom_b, p_proj + (size_t)NA * HD, NB, 128, 128);

    // 3. bond scatter-sum
    scatter_kernel<<<(NB + 7) / 8, 256>>>(ab_src, ab_dst);

    // 4. MLP layer 1 (relu)
    gemm_tf32_kernel<true><<<dim3((NA + 127) / 128, 2), 256>>>(
        p_agg, nmlp_w1, nmlp_b1, p_h1, NA, 128, 256);

    // 5. MLP layer 2 + LN + relu + residual + pool
    gemm_ln_pool_tf32_kernel<<<(NA + 127) / 128, 256>>>(
        p_h1, nmlp_w2, nmlp_b2, n_ln_g, n_ln_b, node_graph_id, out);

    // 6. per-graph mean
    finalize_kernel<<<(NG * (HD / 4) + 255) / 256, 256>>>((float4*)out);
}